// round 16
// baseline (speedup 1.0000x reference)
#include <cuda_runtime.h>
#include <float.h>

#define L_SEQ 4096
#define N_TOTAL 512
#define WPB 8            // warps per block
#define TPB (WPB * 32)
#define PAD_MAX 4096     // P <= 4094
#define LP_MAX (L_SEQ + 2 * PAD_MAX)   // 12288 floats = 48KB static shared
#define MAX_B 64

__device__ int g_inv[N_TOTAL];
__device__ int g_P;
__device__ int g_ctr[MAX_B];

// Reset work counters, build inverse permutation, recover P. Cheap O(N).
__global__ void setup_kernel(const int* __restrict__ perm,
                             const int* __restrict__ off0,
                             const int* __restrict__ lout0,
                             int n_perm) {
    int j = threadIdx.x;
    if (j < MAX_B) g_ctr[j] = 0;
    if (j < n_perm) g_inv[perm[j]] = j;
    if (j == 0) {
        int d6  = off0[6] - off0[0];
        int pad = (lout0[0] - L_SEQ + d6) / 2;
        g_P = off0[0] + pad;
    }
}

// Sliding-window conv. Three tiers sharing one window state:
//   (a) paired blocks of 2*KS outputs: both loads of each pair issued up
//       front, two interleaved FMA chains, one mx fold per pair;
//   (b) single KS-output blocks (exact R5 body);
//   (c) direct-tap tail (< KS outputs).
// KS odd => rotation is identity after each block; all slot indices are
// compile-time constants (pure SSA renames, no MOVs).
template<int KS>
__device__ __forceinline__ void conv_lane(
    const float* __restrict__ p, int steps, int d, float bsv,
    const float* __restrict__ wk, float& mx, int& cnt)
{
    if (steps <= 0) return;
    if (steps >= KS) {
        float y[KS];
#pragma unroll
        for (int j = 0; j < KS - 1; j++) y[j] = p[j * d];
        const float* pl = p + (KS - 1) * d;
        int i = 0;

        // (a) paired blocks: 2*KS outputs per branch
        for (; i + 2 * KS <= steps; i += 2 * KS) {
#pragma unroll
            for (int v = 0; v < KS; v++) {
                // outputs u0 = 2v, u1 = 2v+1 (slot arithmetic mod KS)
                float n0 = pl[(2 * v) * d];
                float n1 = pl[(2 * v) * d + d];
                y[(2 * v + KS - 1) % KS] = n0;
                float s0 = bsv;
#pragma unroll
                for (int k = 0; k < KS; k++)
                    s0 = fmaf(wk[k], y[(2 * v + k) % KS], s0);
                y[(2 * v) % KS] = n1;            // SSA: s0 consumed old value
                float s1 = bsv;
#pragma unroll
                for (int k = 0; k < KS; k++)
                    s1 = fmaf(wk[k], y[(2 * v + 1 + k) % KS], s1);
                mx = fmaxf(mx, fmaxf(s0, s1));
                cnt += (s0 > 0.0f);
                cnt += (s1 > 0.0f);
            }
            pl += 2 * KS * d;
        }

        // (b) one more single block if KS <= remaining < 2*KS (R5 body)
        for (; i + KS <= steps; i += KS) {
#pragma unroll
            for (int u = 0; u < KS; u++) {
                y[(u + KS - 1) % KS] = *pl; pl += d;
                float s = bsv;
#pragma unroll
                for (int k = 0; k < KS; k++)
                    s = fmaf(wk[k], y[(u + k) % KS], s);
                mx = fmaxf(mx, s);
                cnt += (s > 0.0f);
            }
        }

        // (c) direct tail
        for (; i < steps; i++) {
            const float* q = p + i * d;
            float s = bsv;
#pragma unroll
            for (int k = 0; k < KS; k++) s = fmaf(wk[k], q[k * d], s);
            mx = fmaxf(mx, s);
            cnt += (s > 0.0f);
        }
    } else {
        for (int i = 0; i < steps; i++) {
            const float* q = p + i * d;
            float s = bsv;
#pragma unroll
            for (int k = 0; k < KS; k++) s = fmaf(wk[k], q[k * d], s);
            mx = fmaxf(mx, s);
            cnt += (s > 0.0f);
        }
    }
}

template<int KS>
__device__ __forceinline__ void run_group(
    const float* __restrict__ sx,          // zero-padded: x lives at [P, P+L)
    const float* __restrict__ w, const float* __restrict__ bias,
    const int*  __restrict__ off, const int* __restrict__ lout,
    float* __restrict__ out, int gi, int base, int b, int stride)
{
    const int lane = threadIdx.x & 31;

    float wk[KS];
#pragma unroll
    for (int k = 0; k < KS; k++) wk[k] = __ldg(&w[gi * KS + k]);
    const int   o0  = __ldg(&off[gi * KS]);           // padded-array base for tap 0
    const int   d   = __ldg(&off[gi * KS + 1]) - o0;  // dilation
    const float bsv = __ldg(&bias[gi]);
    const int   lo  = __ldg(&lout[gi]);

    float mx  = -FLT_MAX;
    int   cnt = 0;
    const float* px = sx + o0;

    if (d < 32) {
        // lane -> (residue r, chunk g); uniform odd chunk size => conflict-free banks
        const int r = lane % d;
        const int g = lane / d;
        const int Mmax = (lo + d - 1) / d;
        const int Gmin = 32 / d;
        int mc = (Mmax + Gmin - 1) / Gmin;
        mc |= 1;                                   // round up to odd
        const int Mr = (r < lo) ? (lo - r + d - 1) / d : 0;
        int m0 = g * mc;
        int m1 = m0 + mc; if (m1 > Mr) m1 = Mr;
        if (m0 < m1)
            conv_lane<KS>(px + r + d * m0, m1 - m0, d, bsv, wk, mx, cnt);
    } else {
        // lanes = consecutive residues (consecutive addresses: conflict-free)
        for (int rb = 0; rb < d; rb += 32) {
            const int r = rb + lane;
            if (r < d) {
                const int Mr = (r < lo) ? (lo - r + d - 1) / d : 0;
                conv_lane<KS>(px + r, Mr, d, bsv, wk, mx, cnt);
            }
        }
    }

    // warp reductions
#pragma unroll
    for (int o = 16; o; o >>= 1) {
        mx   = fmaxf(mx, __shfl_xor_sync(0xffffffffu, mx, o));
        cnt += __shfl_xor_sync(0xffffffffu, cnt, o);
    }

    if (lane == 0) {
        int col = g_inv[base + gi];
        out[b * stride + 2 * col]     = mx;
        out[b * stride + 2 * col + 1] = (float)cnt / (float)lo;
    }
}

__global__ __launch_bounds__(TPB)
void rocket_all_kernel(
    const float* __restrict__ x,
    const float* __restrict__ w0, const float* __restrict__ b0,
    const int*  __restrict__ off0, const int* __restrict__ lout0, int n0,
    const float* __restrict__ w1, const float* __restrict__ b1,
    const int*  __restrict__ off1, const int* __restrict__ lout1, int n1,
    const float* __restrict__ w2, const float* __restrict__ b2,
    const int*  __restrict__ off2, const int* __restrict__ lout2, int n2,
    float* __restrict__ out, int stride)
{
    __shared__ float sx[LP_MAX];
    const int b = blockIdx.y;
    const int P = g_P;
    const int N = n0 + n1 + n2;

    // zero pad regions [0,P) and [P+L, P+L+P)
    for (int i = threadIdx.x; i < P; i += TPB) {
        sx[i]             = 0.0f;
        sx[P + L_SEQ + i] = 0.0f;
    }
    // stage x[b] into sx[P .. P+L): P even => float2-aligned
    {
        const float2* xb2 = (const float2*)(x + (size_t)b * L_SEQ);
        float2* dst = (float2*)(sx + P);
        for (int i = threadIdx.x; i < L_SEQ / 2; i += TPB)
            dst[i] = xb2[i];
    }
    __syncthreads();

    const int lane = threadIdx.x & 31;

    // warp-granular work stealing over kernels for this batch
    for (;;) {
        int item = 0;
        if (lane == 0) item = atomicAdd(&g_ctr[b], 1);
        item = __shfl_sync(0xffffffffu, item, 0);
        if (item >= N) break;

        if (item < n0) {
            run_group<7>(sx, w0, b0, off0, lout0, out, item, 0, b, stride);
        } else if (item < n0 + n1) {
            run_group<9>(sx, w1, b1, off1, lout1, out, item - n0, n0, b, stride);
        } else {
            run_group<11>(sx, w2, b2, off2, lout2, out, item - n0 - n1, n0 + n1, b, stride);
        }
    }
}

extern "C" void kernel_launch(void* const* d_in, const int* in_sizes, int n_in,
                              void* d_out, int out_size) {
    // Dict order:      x, perm, P, w0,b0,off0,lout0, w1,b1,off1,lout1, w2,b2,off2,lout2
    // Signature order: x, w0,b0,off0,lout0, w1,b1,off1,lout1, w2,b2,off2,lout2, perm, P
    int ix, iperm, ig0, ig1, ig2;
    if (n_in >= 3 && in_sizes[1] == N_TOTAL && in_sizes[2] == 1) {
        ix = 0; iperm = 1; ig0 = 3; ig1 = 7; ig2 = 11;
    } else {
        ix = 0; ig0 = 1; ig1 = 5; ig2 = 9; iperm = 13;
    }

    const float* x     = (const float*)d_in[ix];
    const int*   perm  = (const int*)  d_in[iperm];

    const float* w0    = (const float*)d_in[ig0 + 0];
    const float* b0    = (const float*)d_in[ig0 + 1];
    const int*   off0  = (const int*)  d_in[ig0 + 2];
    const int*   lout0 = (const int*)  d_in[ig0 + 3];
    const float* w1    = (const float*)d_in[ig1 + 0];
    const float* b1    = (const float*)d_in[ig1 + 1];
    const int*   off1  = (const int*)  d_in[ig1 + 2];
    const int*   lout1 = (const int*)  d_in[ig1 + 3];
    const float* w2    = (const float*)d_in[ig2 + 0];
    const float* b2    = (const float*)d_in[ig2 + 1];
    const int*   off2  = (const int*)  d_in[ig2 + 2];
    const int*   lout2 = (const int*)  d_in[ig2 + 3];

    const int n0 = in_sizes[ig0 + 1];
    const int n1 = in_sizes[ig1 + 1];
    const int n2 = in_sizes[ig2 + 1];
    const int B  = in_sizes[ix] / L_SEQ;
    const int N  = n0 + n1 + n2;
    const int stride = 2 * N;

    setup_kernel<<<1, N_TOTAL>>>(perm, off0, lout0, in_sizes[iperm]);

    // persistent balanced grid: ~4 blocks/SM * 148 SMs
    int bpb = 592 / (B > 0 ? B : 1);
    if (bpb < 1) bpb = 1;
    int max_bpb = (N + WPB - 1) / WPB;
    if (bpb > max_bpb) bpb = max_bpb;

    dim3 grid(bpb, B);
    rocket_all_kernel<<<grid, TPB>>>(
        x,
        w0, b0, off0, lout0, n0,
        w1, b1, off1, lout1, n1,
        w2, b2, off2, lout2, n2,
        (float*)d_out, stride);
}

// round 17
// speedup vs baseline: 1.5533x; 1.5533x over previous
#include <cuda_runtime.h>
#include <float.h>

#define L_SEQ 4096
#define N_TOTAL 512
#define WPB 8            // warps per block
#define TPB (WPB * 32)
#define PAD_MAX 4096     // P <= 4094
#define LP_MAX (L_SEQ + 2 * PAD_MAX)   // 12288 floats = 48KB static shared
#define MAX_B 64

__device__ int g_inv[N_TOTAL];
__device__ int g_P;
__device__ int g_ctr[MAX_B];

// Reset work counters, build inverse permutation, recover P. Cheap O(N).
__global__ void setup_kernel(const int* __restrict__ perm,
                             const int* __restrict__ off0,
                             const int* __restrict__ lout0,
                             int n_perm) {
    int j = threadIdx.x;
    if (j < MAX_B) g_ctr[j] = 0;
    if (j < n_perm) g_inv[perm[j]] = j;
    if (j == 0) {
        int d6  = off0[6] - off0[0];
        int pad = (lout0[0] - L_SEQ + d6) / 2;
        g_P = off0[0] + pad;
    }
}

// Sliding-window conv with a one-deep software-pipelined load:
// while computing output j's FMA chain, the LDS for output j+1's new tap is
// already in flight (nv). y[slot] = nv is an SSA rename (nv immediately
// redefined), so instruction count matches R5 while the 29-cyc LDS latency
// hides under the ~KS*4-cyc chain.
// Pipelined loop covers outputs [0, steps-1); tail uses direct taps.
// Lookahead load for output j reads tap (j+KS)*d <= (steps-1+KS-1)*d = the
// last legal tap of output steps-1 -> always in the padded array.
template<int KS>
__device__ __forceinline__ void conv_lane(
    const float* __restrict__ p, int steps, int d, float bsv,
    const float* __restrict__ wk, float& mx, int& cnt)
{
    if (steps <= 0) return;
    if (steps > KS) {
        float y[KS];
#pragma unroll
        for (int j = 0; j < KS - 1; j++) y[j] = p[j * d];
        float nv = p[(KS - 1) * d];        // pending new tap for output 0
        const float* pl = p + KS * d;      // load address for output 1
        int i = 0;
        const int lim = steps - 1;         // pipelined outputs [0, lim)
        for (; i + KS <= lim; i += KS) {
#pragma unroll
            for (int u = 0; u < KS; u++) {
                y[(u + KS - 1) % KS] = nv; // rename: completes window for output i+u
                nv = *pl; pl += d;         // prefetch output i+u+1's new tap
                float s = bsv;
#pragma unroll
                for (int k = 0; k < KS; k++)
                    s = fmaf(wk[k], y[(u + k) % KS], s);
                mx = fmaxf(mx, s);
                cnt += (s > 0.0f);
            }
        }
        // tail: outputs i..steps-1 via direct taps (<= KS + remainder outputs)
        for (; i < steps; i++) {
            const float* q = p + i * d;
            float s = bsv;
#pragma unroll
            for (int k = 0; k < KS; k++) s = fmaf(wk[k], q[k * d], s);
            mx = fmaxf(mx, s);
            cnt += (s > 0.0f);
        }
    } else {
        for (int i = 0; i < steps; i++) {
            const float* q = p + i * d;
            float s = bsv;
#pragma unroll
            for (int k = 0; k < KS; k++) s = fmaf(wk[k], q[k * d], s);
            mx = fmaxf(mx, s);
            cnt += (s > 0.0f);
        }
    }
}

template<int KS>
__device__ __forceinline__ void run_group(
    const float* __restrict__ sx,          // zero-padded: x lives at [P, P+L)
    const float* __restrict__ w, const float* __restrict__ bias,
    const int*  __restrict__ off, const int* __restrict__ lout,
    float* __restrict__ out, int gi, int base, int b, int stride)
{
    const int lane = threadIdx.x & 31;

    float wk[KS];
#pragma unroll
    for (int k = 0; k < KS; k++) wk[k] = __ldg(&w[gi * KS + k]);
    const int   o0  = __ldg(&off[gi * KS]);           // padded-array base for tap 0
    const int   d   = __ldg(&off[gi * KS + 1]) - o0;  // dilation
    const float bsv = __ldg(&bias[gi]);
    const int   lo  = __ldg(&lout[gi]);

    float mx  = -FLT_MAX;
    int   cnt = 0;
    const float* px = sx + o0;

    if (d < 32) {
        // lane -> (residue r, chunk g); uniform odd chunk size => conflict-free banks
        const int r = lane % d;
        const int g = lane / d;
        const int Mmax = (lo + d - 1) / d;
        const int Gmin = 32 / d;
        int mc = (Mmax + Gmin - 1) / Gmin;
        mc |= 1;                                   // round up to odd
        const int Mr = (r < lo) ? (lo - r + d - 1) / d : 0;
        int m0 = g * mc;
        int m1 = m0 + mc; if (m1 > Mr) m1 = Mr;
        if (m0 < m1)
            conv_lane<KS>(px + r + d * m0, m1 - m0, d, bsv, wk, mx, cnt);
    } else {
        // lanes = consecutive residues (consecutive addresses: conflict-free)
        for (int rb = 0; rb < d; rb += 32) {
            const int r = rb + lane;
            if (r < d) {
                const int Mr = (r < lo) ? (lo - r + d - 1) / d : 0;
                conv_lane<KS>(px + r, Mr, d, bsv, wk, mx, cnt);
            }
        }
    }

    // warp reductions
#pragma unroll
    for (int o = 16; o; o >>= 1) {
        mx   = fmaxf(mx, __shfl_xor_sync(0xffffffffu, mx, o));
        cnt += __shfl_xor_sync(0xffffffffu, cnt, o);
    }

    if (lane == 0) {
        int col = g_inv[base + gi];
        out[b * stride + 2 * col]     = mx;
        out[b * stride + 2 * col + 1] = (float)cnt / (float)lo;
    }
}

__global__ __launch_bounds__(TPB)
void rocket_all_kernel(
    const float* __restrict__ x,
    const float* __restrict__ w0, const float* __restrict__ b0,
    const int*  __restrict__ off0, const int* __restrict__ lout0, int n0,
    const float* __restrict__ w1, const float* __restrict__ b1,
    const int*  __restrict__ off1, const int* __restrict__ lout1, int n1,
    const float* __restrict__ w2, const float* __restrict__ b2,
    const int*  __restrict__ off2, const int* __restrict__ lout2, int n2,
    float* __restrict__ out, int stride)
{
    __shared__ float sx[LP_MAX];
    const int b = blockIdx.y;
    const int P = g_P;
    const int N = n0 + n1 + n2;

    // zero pad regions [0,P) and [P+L, P+L+P)
    for (int i = threadIdx.x; i < P; i += TPB) {
        sx[i]             = 0.0f;
        sx[P + L_SEQ + i] = 0.0f;
    }
    // stage x[b] into sx[P .. P+L): P even => float2-aligned
    {
        const float2* xb2 = (const float2*)(x + (size_t)b * L_SEQ);
        float2* dst = (float2*)(sx + P);
        for (int i = threadIdx.x; i < L_SEQ / 2; i += TPB)
            dst[i] = xb2[i];
    }
    __syncthreads();

    const int lane = threadIdx.x & 31;

    // warp-granular work stealing over kernels for this batch
    for (;;) {
        int item = 0;
        if (lane == 0) item = atomicAdd(&g_ctr[b], 1);
        item = __shfl_sync(0xffffffffu, item, 0);
        if (item >= N) break;

        if (item < n0) {
            run_group<7>(sx, w0, b0, off0, lout0, out, item, 0, b, stride);
        } else if (item < n0 + n1) {
            run_group<9>(sx, w1, b1, off1, lout1, out, item - n0, n0, b, stride);
        } else {
            run_group<11>(sx, w2, b2, off2, lout2, out, item - n0 - n1, n0 + n1, b, stride);
        }
    }
}

extern "C" void kernel_launch(void* const* d_in, const int* in_sizes, int n_in,
                              void* d_out, int out_size) {
    // Dict order:      x, perm, P, w0,b0,off0,lout0, w1,b1,off1,lout1, w2,b2,off2,lout2
    // Signature order: x, w0,b0,off0,lout0, w1,b1,off1,lout1, w2,b2,off2,lout2, perm, P
    int ix, iperm, ig0, ig1, ig2;
    if (n_in >= 3 && in_sizes[1] == N_TOTAL && in_sizes[2] == 1) {
        ix = 0; iperm = 1; ig0 = 3; ig1 = 7; ig2 = 11;
    } else {
        ix = 0; ig0 = 1; ig1 = 5; ig2 = 9; iperm = 13;
    }

    const float* x     = (const float*)d_in[ix];
    const int*   perm  = (const int*)  d_in[iperm];

    const float* w0    = (const float*)d_in[ig0 + 0];
    const float* b0    = (const float*)d_in[ig0 + 1];
    const int*   off0  = (const int*)  d_in[ig0 + 2];
    const int*   lout0 = (const int*)  d_in[ig0 + 3];
    const float* w1    = (const float*)d_in[ig1 + 0];
    const float* b1    = (const float*)d_in[ig1 + 1];
    const int*   off1  = (const int*)  d_in[ig1 + 2];
    const int*   lout1 = (const int*)  d_in[ig1 + 3];
    const float* w2    = (const float*)d_in[ig2 + 0];
    const float* b2    = (const float*)d_in[ig2 + 1];
    const int*   off2  = (const int*)  d_in[ig2 + 2];
    const int*   lout2 = (const int*)  d_in[ig2 + 3];

    const int n0 = in_sizes[ig0 + 1];
    const int n1 = in_sizes[ig1 + 1];
    const int n2 = in_sizes[ig2 + 1];
    const int B  = in_sizes[ix] / L_SEQ;
    const int N  = n0 + n1 + n2;
    const int stride = 2 * N;

    setup_kernel<<<1, N_TOTAL>>>(perm, off0, lout0, in_sizes[iperm]);

    // persistent balanced grid: ~4 blocks/SM * 148 SMs
    int bpb = 592 / (B > 0 ? B : 1);
    if (bpb < 1) bpb = 1;
    int max_bpb = (N + WPB - 1) / WPB;
    if (bpb > max_bpb) bpb = max_bpb;

    dim3 grid(bpb, B);
    rocket_all_kernel<<<grid, TPB>>>(
        x,
        w0, b0, off0, lout0, n0,
        w1, b1, off1, lout1, n1,
        w2, b2, off2, lout2, n2,
        (float*)d_out, stride);
}